// round 1
// baseline (speedup 1.0000x reference)
#include <cuda_runtime.h>
#include <cstdint>

// snn_input: integrate-and-fire over T=32 steps, N=4194304 neurons.
//   per step: m += image[t]; spk = m >= 1.0f; m -= 1.0f if spk
// Output: [spikes (T*N, as 0/1 float32), final mempot (N float32)] concatenated.
// Pure streaming: ~1.06 GB traffic -> HBM-bound, roofline ~160us.

static constexpr int TSTEPS = 32;
static constexpr float THRES = 1.0f;

__global__ __launch_bounds__(256) void snn_if_kernel(
    const float4* __restrict__ image,    // [T, N/4] as float4
    const float4* __restrict__ mempot0,  // [N/4]
    float4* __restrict__ out,            // [T*N/4 spikes][N/4 mempot]
    int n4)
{
    int i = blockIdx.x * blockDim.x + threadIdx.x;
    if (i >= n4) return;

    float4 m = __ldcs(&mempot0[i]);

#pragma unroll
    for (int t = 0; t < TSTEPS; t++) {
        float4 im = __ldcs(&image[(size_t)t * n4 + i]);
        m.x += im.x; m.y += im.y; m.z += im.z; m.w += im.w;
        float4 s;
        s.x = (m.x >= THRES) ? 1.0f : 0.0f;
        s.y = (m.y >= THRES) ? 1.0f : 0.0f;
        s.z = (m.z >= THRES) ? 1.0f : 0.0f;
        s.w = (m.w >= THRES) ? 1.0f : 0.0f;
        // thres == 1.0 so m -= s*THRES == m -= s
        m.x -= s.x; m.y -= s.y; m.z -= s.z; m.w -= s.w;
        __stcs(&out[(size_t)t * n4 + i], s);
    }
    __stcs(&out[(size_t)TSTEPS * n4 + i], m);
}

extern "C" void kernel_launch(void* const* d_in, const int* in_sizes, int n_in,
                              void* d_out, int out_size)
{
    const float4* image   = (const float4*)d_in[0];
    const float4* mempot0 = (const float4*)d_in[1];
    float4*       out     = (float4*)d_out;

    int n  = in_sizes[1];      // 4194304 neurons
    int n4 = n / 4;            // 1048576 float4 lanes

    const int threads = 256;
    const int blocks  = (n4 + threads - 1) / threads;
    snn_if_kernel<<<blocks, threads>>>(image, mempot0, out, n4);
}

// round 2
// speedup vs baseline: 1.0148x; 1.0148x over previous
#include <cuda_runtime.h>
#include <cstdint>

// snn_input: integrate-and-fire over T=32 steps, N=4194304 neurons.
//   per step: m += image[t]; spk = m >= 1.0f; m -= 1.0f if spk
// Output: [spikes (T*N, as 0/1 float32), final mempot (N float32)].
// HBM-bound (1.056 GB traffic). R2: batch 8 timesteps of loads per thread
// (MLP=8) to fill the LSU queue and coarsen DRAM read/write bursts.

static constexpr int TSTEPS = 32;
static constexpr int TBATCH = 8;
static constexpr float THRES = 1.0f;

__global__ __launch_bounds__(256) void snn_if_kernel(
    const float4* __restrict__ image,    // [T, N/4] as float4
    const float4* __restrict__ mempot0,  // [N/4]
    float4* __restrict__ out,            // [T*N/4 spikes][N/4 mempot]
    int n4)
{
    int i = blockIdx.x * blockDim.x + threadIdx.x;
    if (i >= n4) return;

    float4 m = __ldcs(&mempot0[i]);

#pragma unroll
    for (int tb = 0; tb < TSTEPS / TBATCH; tb++) {
        float4 im[TBATCH];
        // front-batched loads: 8 independent LDG.E.128.CS in flight
#pragma unroll
        for (int j = 0; j < TBATCH; j++) {
            im[j] = __ldcs(&image[(size_t)(tb * TBATCH + j) * n4 + i]);
        }
        // compute + store burst
#pragma unroll
        for (int j = 0; j < TBATCH; j++) {
            m.x += im[j].x; m.y += im[j].y; m.z += im[j].z; m.w += im[j].w;
            float4 s;
            s.x = (m.x >= THRES) ? 1.0f : 0.0f;
            s.y = (m.y >= THRES) ? 1.0f : 0.0f;
            s.z = (m.z >= THRES) ? 1.0f : 0.0f;
            s.w = (m.w >= THRES) ? 1.0f : 0.0f;
            // thres == 1.0 so subtracting s == subtracting s*THRES
            m.x -= s.x; m.y -= s.y; m.z -= s.z; m.w -= s.w;
            __stcs(&out[(size_t)(tb * TBATCH + j) * n4 + i], s);
        }
    }
    __stcs(&out[(size_t)TSTEPS * n4 + i], m);
}

extern "C" void kernel_launch(void* const* d_in, const int* in_sizes, int n_in,
                              void* d_out, int out_size)
{
    const float4* image   = (const float4*)d_in[0];
    const float4* mempot0 = (const float4*)d_in[1];
    float4*       out     = (float4*)d_out;

    int n  = in_sizes[1];      // 4194304 neurons
    int n4 = n / 4;            // 1048576 float4 lanes

    const int threads = 256;
    const int blocks  = (n4 + threads - 1) / threads;
    snn_if_kernel<<<blocks, threads>>>(image, mempot0, out, n4);
}